// round 2
// baseline (speedup 1.0000x reference)
#include <cuda_runtime.h>
#include <math.h>
#include <float.h>

#define BB 8
#define NN 4096
#define SS 1024
#define KK 32
#define PP (BB*SS*KK)
#define BS (BB*SS)

__device__ float d_newxyz[BS*3];
__device__ int   d_fpsidx[BS];
__device__ int   d_knn[PP];
__device__ float d_geo[(size_t)PP*7];
__device__ float d_augy[(size_t)PP*32];
__device__ float d_ptsT[(size_t)BB*NN*64];
__device__ float d_x1[(size_t)PP*96];
__device__ float d_fx1[(size_t)BS*96];
__device__ float d_y1[(size_t)PP*64];
__device__ float d_fy1[(size_t)BS*64];
__device__ float d_y2[(size_t)PP*128];
__device__ float d_fy2[(size_t)BS*128];
__device__ float d_cf[(size_t)BS*128];
__device__ float d_x3[(size_t)PP*135];
__device__ float d_y3[(size_t)PP*128];
__device__ float d_part[1024*256];
__device__ float d_bnp_aug[64];
__device__ float d_bnp1[128];
__device__ float d_bnp1f[128];
__device__ float d_bnp2[256];
__device__ float d_bnp2f[256];
__device__ float d_bnp3[256];

// ---- transpose points (B,64,N) -> (B,N,64) ----
__global__ void k_ptsT(const float* __restrict__ pts) {
    __shared__ float t[32][33];
    int b = blockIdx.z, c0 = blockIdx.y*32, n0 = blockIdx.x*32;
    int tx = threadIdx.x, ty = threadIdx.y;
    #pragma unroll
    for (int i = 0; i < 32; i += 8)
        t[ty+i][tx] = pts[(size_t)b*64*NN + (size_t)(c0+ty+i)*NN + n0 + tx];
    __syncthreads();
    #pragma unroll
    for (int i = 0; i < 32; i += 8)
        d_ptsT[((size_t)b*NN + n0+ty+i)*64 + c0+tx] = t[tx][ty+i];
}

// ---- FPS ----
__global__ void __launch_bounds__(1024) k_fps(const float* __restrict__ xyz,
                                              float* __restrict__ out) {
    int b = blockIdx.x, tid = threadIdx.x;
    const float* xb = xyz + (size_t)b*3*NN;
    float px[4], py[4], pz[4], dist[4];
    #pragma unroll
    for (int t = 0; t < 4; t++) {
        int n = t*1024 + tid;
        px[t] = xb[n]; py[t] = xb[NN+n]; pz[t] = xb[2*NN+n];
        dist[t] = 1e10f;
    }
    __shared__ unsigned long long red[32];
    __shared__ int s_far;
    int far = 0;
    for (int it = 0; it < SS; it++) {
        float cx = xb[far], cy = xb[NN+far], cz = xb[2*NN+far];
        if (tid == 0) {
            d_fpsidx[b*SS+it] = far;
            d_newxyz[((size_t)b*SS+it)*3+0] = cx;
            d_newxyz[((size_t)b*SS+it)*3+1] = cy;
            d_newxyz[((size_t)b*SS+it)*3+2] = cz;
            out[b*3072 + it]        = cx;
            out[b*3072 + 1024 + it] = cy;
            out[b*3072 + 2048 + it] = cz;
        }
        unsigned long long key = 0ull;
        #pragma unroll
        for (int t = 0; t < 4; t++) {
            float dx = px[t]-cx, dy = py[t]-cy, dz = pz[t]-cz;
            float d = __fadd_rn(__fadd_rn(__fmul_rn(dx,dx), __fmul_rn(dy,dy)), __fmul_rn(dz,dz));
            dist[t] = fminf(dist[t], d);
            unsigned long long k2 = ((unsigned long long)__float_as_uint(dist[t]) << 32)
                                  | (unsigned)(~(t*1024 + tid));
            if (k2 > key) key = k2;
        }
        #pragma unroll
        for (int off = 16; off; off >>= 1) {
            unsigned long long o = __shfl_down_sync(0xffffffffu, key, off);
            if (o > key) key = o;
        }
        if ((tid & 31) == 0) red[tid >> 5] = key;
        __syncthreads();
        if (tid < 32) {
            key = red[tid];
            #pragma unroll
            for (int off = 16; off; off >>= 1) {
                unsigned long long o = __shfl_down_sync(0xffffffffu, key, off);
                if (o > key) key = o;
            }
            if (tid == 0) s_far = (int)(~(unsigned)key);
        }
        __syncthreads();
        far = s_far;
    }
}

// ---- KNN: exact 33 smallest, drop min ----
__global__ void __launch_bounds__(128) k_knn(const float* __restrict__ xyz) {
    __shared__ float sx[NN], sy[NN], sz[NN];
    int b = blockIdx.y;
    const float* xb = xyz + (size_t)b*3*NN;
    for (int j = threadIdx.x; j < NN; j += 128) {
        sx[j] = xb[j]; sy[j] = xb[NN+j]; sz[j] = xb[2*NN+j];
    }
    __syncthreads();
    int q = blockIdx.x*128 + threadIdx.x;
    float qx = d_newxyz[((size_t)b*SS+q)*3+0];
    float qy = d_newxyz[((size_t)b*SS+q)*3+1];
    float qz = d_newxyz[((size_t)b*SS+q)*3+2];
    float sq = __fadd_rn(__fadd_rn(__fmul_rn(qx,qx), __fmul_rn(qy,qy)), __fmul_rn(qz,qz));
    float kd[33]; int ki[33];
    int cnt = 0; float cm = 0.f; int cmi = 0, cms = 0;
    for (int j = 0; j < NN; j++) {
        float x = sx[j], y = sy[j], z = sz[j];
        float sn  = __fadd_rn(__fadd_rn(__fmul_rn(x,x), __fmul_rn(y,y)), __fmul_rn(z,z));
        float dot = __fadd_rn(__fadd_rn(__fmul_rn(x,qx), __fmul_rn(y,qy)), __fmul_rn(z,qz));
        float d2  = __fsub_rn(__fadd_rn(sn, sq), __fmul_rn(2.f, dot));
        if (cnt < 33) {
            kd[cnt] = d2; ki[cnt] = j; cnt++;
            if (cnt == 33) {
                cm = kd[0]; cmi = ki[0]; cms = 0;
                for (int i = 1; i < 33; i++)
                    if (kd[i] > cm || (kd[i] == cm && ki[i] > cmi)) { cm = kd[i]; cmi = ki[i]; cms = i; }
            }
        } else if (d2 < cm) {
            kd[cms] = d2; ki[cms] = j;
            cm = kd[0]; cmi = ki[0]; cms = 0;
            for (int i = 1; i < 33; i++)
                if (kd[i] > cm || (kd[i] == cm && ki[i] > cmi)) { cm = kd[i]; cmi = ki[i]; cms = i; }
        }
    }
    float mn = kd[0]; int mni = ki[0], mns = 0;
    for (int i = 1; i < 33; i++)
        if (kd[i] < mn || (kd[i] == mn && ki[i] < mni)) { mn = kd[i]; mni = ki[i]; mns = i; }
    int* dst = &d_knn[((size_t)b*SS+q)*KK];
    int w = 0;
    for (int i = 0; i < 33; i++)
        if (i != mns) dst[w++] = ki[i];
}

// ---- aug features + conv_aug (pre-BN) ----
__global__ void __launch_bounds__(256) k_aug(const float* __restrict__ xyz,
                                             const float* __restrict__ Waug,
                                             const float* __restrict__ baug) {
    __shared__ float sW[320];
    __shared__ float sb[32];
    __shared__ float sx[8][10];
    int tid = threadIdx.x;
    for (int i = tid; i < 320; i += 256) sW[i] = Waug[i];
    if (tid < 32) sb[tid] = baug[tid];
    int kk = tid >> 5, c = tid & 31;
    int p = blockIdx.x*8 + kk;
    int b = p >> 15;
    if (c == 0) {
        int s = (p >> 5) & 1023;
        const float* nx = &d_newxyz[((size_t)b*SS + s)*3];
        float cx = nx[0], cy = nx[1], cz = nx[2];
        int gi = d_knn[p];
        const float* xb = xyz + (size_t)b*3*NN;
        float gx = xb[gi], gy = xb[NN+gi], gz = xb[2*NN+gi];
        float dx = gx-cx, dy = gy-cy, dz = gz-cz;
        float n0 = __fmul_rn(dx,dx), n1 = __fmul_rn(dy,dy), n2 = __fmul_rn(dz,dz);
        float gd = sqrtf(__fadd_rn(__fadd_rn(n0,n1),n2));
        sx[kk][0]=cx; sx[kk][1]=cy; sx[kk][2]=cz;
        sx[kk][3]=gx; sx[kk][4]=gy; sx[kk][5]=gz;
        sx[kk][6]=n0; sx[kk][7]=n1; sx[kk][8]=n2; sx[kk][9]=gd;
    }
    __syncthreads();
    if (c < 7) {
        int src = (c < 6) ? c : 9;
        d_geo[(size_t)p*7 + c] = sx[kk][src];
    }
    float acc = sb[c];
    #pragma unroll
    for (int i = 0; i < 10; i++) acc = fmaf(sx[kk][i], sW[c*10+i], acc);
    d_augy[(size_t)p*32 + c] = acc;
}

// ---- deterministic column stats ----
__global__ void __launch_bounds__(256) k_colstats(const float* __restrict__ Y,
                                                  int M, int C, float* __restrict__ part) {
    int strip = blockIdx.x, nstrip = gridDim.x;
    int rows = M / nstrip;
    int r0 = strip * rows;
    int G = 256 / C;
    int g = threadIdx.x / C, c = threadIdx.x % C;
    float s = 0.f, q = 0.f;
    for (int m = r0 + g; m < r0 + rows; m += G) {
        float v = Y[(size_t)m*C + c];
        s += v; q = fmaf(v, v, q);
    }
    __shared__ float sh[512];
    sh[threadIdx.x] = s; sh[256 + threadIdx.x] = q;
    __syncthreads();
    if (g == 0) {
        for (int gg = 1; gg < G; gg++) { s += sh[gg*C + c]; q += sh[256 + gg*C + c]; }
        part[(size_t)strip*2*C + c]     = s;
        part[(size_t)strip*2*C + C + c] = q;
    }
}

__global__ void k_finalize(const float* __restrict__ part, int nstrip, int M,
                           const float* __restrict__ gamma, const float* __restrict__ beta,
                           float* __restrict__ bnp) {
    int c = threadIdx.x, C = blockDim.x;
    float s = 0.f, q = 0.f;
    for (int j = 0; j < nstrip; j++) {
        s += part[(size_t)j*2*C + c];
        q += part[(size_t)j*2*C + C + c];
    }
    float invM = 1.f / (float)M;
    float mean = s * invM;
    float var = q * invM - mean*mean;
    float scale = gamma[c] * rsqrtf(var + 1e-5f);
    bnp[c] = scale;
    bnp[C + c] = beta[c] - mean*scale;
}

// ---- build x1 ----
__global__ void __launch_bounds__(192) k_x1() {
    int tid = threadIdx.x;
    int pslot = tid / 96, c = tid % 96;
    int p = blockIdx.x*2 + pslot;
    int b = p >> 15;
    if (c < 64) {
        int gi = d_knn[p];
        d_x1[(size_t)p*96 + c] = d_ptsT[((size_t)b*NN + gi)*64 + c];
    } else {
        int ca = c - 64;
        float v = d_augy[(size_t)p*32 + ca];
        d_x1[(size_t)p*96 + c] = fmaxf(fmaf(v, d_bnp_aug[ca], d_bnp_aug[32+ca]), 0.f);
    }
}

// ---- build fx1 ----
__global__ void __launch_bounds__(96) k_fx1() {
    int bs = blockIdx.x, c = threadIdx.x;
    int b = bs >> 10;
    if (c < 64) {
        int gi = d_fpsidx[bs];
        d_fx1[(size_t)bs*96 + c] = d_ptsT[((size_t)b*NN + gi)*64 + c];
    } else {
        int ca = c - 64;
        float sc = d_bnp_aug[ca], sh = d_bnp_aug[32+ca];
        float m = -FLT_MAX;
        for (int k = 0; k < KK; k++) {
            float v = fmaxf(fmaf(d_augy[((size_t)bs*KK + k)*32 + ca], sc, sh), 0.f);
            m = fmaxf(m, v);
        }
        d_fx1[(size_t)bs*96 + c] = m;
    }
}

// ---- GEMM: Y[M,C] = f(X)[M,K] @ W[C,K]^T + bias; optional BN+relu on X ----
__global__ void __launch_bounds__(256) k_gemm(const float* __restrict__ X,
                                              const float* __restrict__ W,
                                              const float* __restrict__ bias,
                                              float* __restrict__ Y,
                                              int M, int K, int C,
                                              const float* __restrict__ bnp) {
    __shared__ float As[16][64];
    __shared__ float Bs[16][64];
    int bm = blockIdx.y * 64, bn = blockIdx.x * 64;
    int tid = threadIdx.x;
    int tx = tid & 15, ty = tid >> 4;
    float acc[4][4];
    #pragma unroll
    for (int i = 0; i < 4; i++)
        #pragma unroll
        for (int j = 0; j < 4; j++) acc[i][j] = 0.f;
    int lr = tid >> 2;
    int lk = (tid & 3) * 4;
    for (int k0 = 0; k0 < K; k0 += 16) {
        #pragma unroll
        for (int u = 0; u < 4; u++) {
            int k = k0 + lk + u;
            float v = 0.f, w = 0.f;
            if (k < K) {
                v = X[(size_t)(bm + lr)*K + k];
                if (bnp) v = fmaxf(fmaf(v, bnp[k], bnp[K + k]), 0.f);
                w = W[(size_t)(bn + lr)*K + k];
            }
            As[lk + u][lr] = v;
            Bs[lk + u][lr] = w;
        }
        __syncthreads();
        #pragma unroll
        for (int kk = 0; kk < 16; kk++) {
            float4 a  = *reinterpret_cast<const float4*>(&As[kk][ty*4]);
            float4 b4 = *reinterpret_cast<const float4*>(&Bs[kk][tx*4]);
            float av[4] = {a.x, a.y, a.z, a.w};
            float bv[4] = {b4.x, b4.y, b4.z, b4.w};
            #pragma unroll
            for (int i = 0; i < 4; i++)
                #pragma unroll
                for (int j = 0; j < 4; j++)
                    acc[i][j] = fmaf(av[i], bv[j], acc[i][j]);
        }
        __syncthreads();
    }
    #pragma unroll
    for (int i = 0; i < 4; i++) {
        int row = bm + ty*4 + i;
        #pragma unroll
        for (int j = 0; j < 4; j++) {
            int col = bn + tx*4 + j;
            Y[(size_t)row*C + col] = acc[i][j] + bias[col];
        }
    }
}

// ---- centre_feat ----
__global__ void __launch_bounds__(256) k_cf() {
    int i = blockIdx.x*256 + threadIdx.x;
    int c = i & 127;
    d_cf[i] = fmaxf(fmaf(d_fy2[i], d_bnp2f[c], d_bnp2f[128+c]), 0.f);
}

// ---- build x3 ----
__global__ void __launch_bounds__(256) k_x3() {
    int tid = threadIdx.x;
    int p = blockIdx.x*2 + (tid >> 7);
    int c = tid & 127;
    float v = d_y2[(size_t)p*128 + c];
    float np2 = fmaxf(fmaf(v, d_bnp2[c], d_bnp2[128+c]), 0.f);
    float dv = np2 - d_cf[(size_t)(p >> 5)*128 + c];
    d_x3[(size_t)p*135 + 7 + c] = dv;
    if (c < 7) d_x3[(size_t)p*135 + c] = d_geo[(size_t)p*7 + c];
}

// ---- softmax attention pool + output ----
__global__ void __launch_bounds__(128) k_final(float* __restrict__ out) {
    int bs = blockIdx.x, c = threadIdx.x;
    float s3 = d_bnp3[c], h3 = d_bnp3[128+c];
    float s2 = d_bnp2[c], h2 = d_bnp2[128+c];
    float att[32];
    float m = -FLT_MAX;
    #pragma unroll
    for (int k = 0; k < 32; k++) {
        float w = fmaxf(fmaf(d_y3[((size_t)bs*32 + k)*128 + c], s3, h3), 0.f);
        att[k] = w;
        m = fmaxf(m, w);
    }
    float sum = 0.f;
    #pragma unroll
    for (int k = 0; k < 32; k++) {
        float e = expf(att[k] - m);
        att[k] = e;
        sum += e;
    }
    float pooled = 0.f;
    #pragma unroll
    for (int k = 0; k < 32; k++) {
        float np2 = fmaxf(fmaf(d_y2[((size_t)bs*32 + k)*128 + c], s2, h2), 0.f);
        pooled = fmaf(att[k], np2, pooled);
    }
    float o = d_cf[(size_t)bs*128 + c] + pooled / sum;
    int b = bs >> 10, s = bs & 1023;
    out[24576 + ((size_t)b*128 + c)*1024 + s] = o;
}

extern "C" void kernel_launch(void* const* d_in, const int* in_sizes, int n_in,
                              void* d_out, int out_size) {
    (void)in_sizes; (void)n_in; (void)out_size;
    const float* xyz    = (const float*)d_in[0];
    const float* points = (const float*)d_in[1];
    const float* W_aug  = (const float*)d_in[2];
    const float* b_aug  = (const float*)d_in[3];
    const float* g_aug  = (const float*)d_in[4];
    const float* be_aug = (const float*)d_in[5];
    const float* W1     = (const float*)d_in[6];
    const float* b1     = (const float*)d_in[7];
    const float* g1     = (const float*)d_in[8];
    const float* be1    = (const float*)d_in[9];
    const float* W2     = (const float*)d_in[10];
    const float* b2     = (const float*)d_in[11];
    const float* g2     = (const float*)d_in[12];
    const float* be2    = (const float*)d_in[13];
    const float* W_laa  = (const float*)d_in[14];
    const float* b_laa  = (const float*)d_in[15];
    const float* g_laa  = (const float*)d_in[16];
    const float* be_laa = (const float*)d_in[17];
    float* out = (float*)d_out;

    void *p_augy, *p_x1, *p_fx1, *p_y1, *p_fy1, *p_y2, *p_fy2, *p_x3, *p_y3, *p_part;
    void *p_bna, *p_bn1, *p_bn1f, *p_bn2, *p_bn2f, *p_bn3;
    cudaGetSymbolAddress(&p_augy, d_augy);
    cudaGetSymbolAddress(&p_x1, d_x1);
    cudaGetSymbolAddress(&p_fx1, d_fx1);
    cudaGetSymbolAddress(&p_y1, d_y1);
    cudaGetSymbolAddress(&p_fy1, d_fy1);
    cudaGetSymbolAddress(&p_y2, d_y2);
    cudaGetSymbolAddress(&p_fy2, d_fy2);
    cudaGetSymbolAddress(&p_x3, d_x3);
    cudaGetSymbolAddress(&p_y3, d_y3);
    cudaGetSymbolAddress(&p_part, d_part);
    cudaGetSymbolAddress(&p_bna, d_bnp_aug);
    cudaGetSymbolAddress(&p_bn1, d_bnp1);
    cudaGetSymbolAddress(&p_bn1f, d_bnp1f);
    cudaGetSymbolAddress(&p_bn2, d_bnp2);
    cudaGetSymbolAddress(&p_bn2f, d_bnp2f);
    cudaGetSymbolAddress(&p_bn3, d_bnp3);

    k_ptsT<<<dim3(NN/32, 2, BB), dim3(32, 8)>>>(points);
    k_fps<<<BB, 1024>>>(xyz, out);
    k_knn<<<dim3(8, BB), 128>>>(xyz);
    k_aug<<<PP/8, 256>>>(xyz, W_aug, b_aug);

    k_colstats<<<1024, 256>>>((const float*)p_augy, PP, 32, (float*)p_part);
    k_finalize<<<1, 32>>>((const float*)p_part, 1024, PP, g_aug, be_aug, (float*)p_bna);

    k_x1<<<PP/2, 192>>>();
    k_fx1<<<BS, 96>>>();

    k_gemm<<<dim3(1, PP/64), 256>>>((const float*)p_x1, W1, b1, (float*)p_y1, PP, 96, 64, nullptr);
    k_gemm<<<dim3(1, BS/64), 256>>>((const float*)p_fx1, W1, b1, (float*)p_fy1, BS, 96, 64, nullptr);

    k_colstats<<<1024, 256>>>((const float*)p_y1, PP, 64, (float*)p_part);
    k_finalize<<<1, 64>>>((const float*)p_part, 1024, PP, g1, be1, (float*)p_bn1);
    k_colstats<<<64, 256>>>((const float*)p_fy1, BS, 64, (float*)p_part);
    k_finalize<<<1, 64>>>((const float*)p_part, 64, BS, g1, be1, (float*)p_bn1f);

    k_gemm<<<dim3(2, PP/64), 256>>>((const float*)p_y1, W2, b2, (float*)p_y2, PP, 64, 128, (const float*)p_bn1);
    k_gemm<<<dim3(2, BS/64), 256>>>((const float*)p_fy1, W2, b2, (float*)p_fy2, BS, 64, 128, (const float*)p_bn1f);

    k_colstats<<<1024, 256>>>((const float*)p_y2, PP, 128, (float*)p_part);
    k_finalize<<<1, 128>>>((const float*)p_part, 1024, PP, g2, be2, (float*)p_bn2);
    k_colstats<<<64, 256>>>((const float*)p_fy2, BS, 128, (float*)p_part);
    k_finalize<<<1, 128>>>((const float*)p_part, 64, BS, g2, be2, (float*)p_bn2f);

    k_cf<<<BS*128/256, 256>>>();
    k_x3<<<PP/2, 256>>>();

    k_gemm<<<dim3(2, PP/64), 256>>>((const float*)p_x3, W_laa, b_laa, (float*)p_y3, PP, 135, 128, nullptr);

    k_colstats<<<1024, 256>>>((const float*)p_y3, PP, 128, (float*)p_part);
    k_finalize<<<1, 128>>>((const float*)p_part, 1024, PP, g_laa, be_laa, (float*)p_bn3);

    k_final<<<BS, 128>>>(out);
}